// round 10
// baseline (speedup 1.0000x reference)
#include <cuda_runtime.h>

// softmax(f[n]+g[m]) over m cancels f[n] -> all output rows identical.
// Single fused kernel, 128 CTAs x 1024 threads (one wave, spin barrier safe):
//   stage A: 64 threads/CTA reduce 64 rows of x with exp(g) weights -> partial
//   barrier: release-atomic arrive + acquire-LDG poll (no ATOMG polling, no L1 flush)
//   stage B: 17 warps reduce partials, 128 threads compute row, all broadcast 4MB.

#define NB 128
#define NT 1024
#define D_IN 16
#define DH   18

__device__ float g_part[17 * NB];        // [col][block]
__device__ unsigned int g_arrive = 0;
__device__ unsigned int g_depart = 0;

__device__ __forceinline__ void atom_add_release_gpu(unsigned int* p) {
    unsigned int old;
    asm volatile("atom.add.release.gpu.global.u32 %0, [%1], 1;"
                 : "=r"(old) : "l"(p) : "memory");
}
__device__ __forceinline__ unsigned int ld_acquire_gpu(const unsigned int* p) {
    unsigned int v;
    asm volatile("ld.acquire.gpu.global.u32 %0, [%1];"
                 : "=r"(v) : "l"(p) : "memory");
    return v;
}

__global__ void __launch_bounds__(NT, 1) fused_kernel(
    const float* __restrict__ x,
    const float* __restrict__ W,
    const float* __restrict__ a,
    const float* __restrict__ Wk,
    float* __restrict__ out)
{
    __shared__ float wa2[16];
    __shared__ float wsum[2][17];
    __shared__ float red[17];
    __shared__ float orow[128];
    int tid  = threadIdx.x;
    int warp = tid >> 5, lane = tid & 31;
    int bid  = blockIdx.x;

    // ---- stage A: rows bid*64 .. bid*64+63, one per thread (warps 0-1) ----
    float4 x0, x1, x2, x3;
    if (tid < 64) {
        const float4* xr = reinterpret_cast<const float4*>(
            x + (size_t)(bid * 64 + tid) * D_IN);
        x0 = xr[0]; x1 = xr[1]; x2 = xr[2]; x3 = xr[3];
    }
    // wa2 = W @ a2 computed by warp 2 (no divergence with loader warps)
    if (tid >= 64 && tid < 80) {
        int r = tid - 64;
        float s = 0.f;
        #pragma unroll
        for (int j = 0; j < DH; ++j) s += W[r * DH + j] * a[DH + j];
        wa2[r] = s;
    }
    // preload Wk column for stage B (warps 0-3); in flight across the barrier
    float wcol[16];
    if (tid < 128) {
        int h = tid >> 4, d = tid & 15;
        const float* Wh = Wk + h * (D_IN * D_IN);
        #pragma unroll
        for (int k = 0; k < 16; ++k) wcol[k] = Wh[k * 16 + d];
    }
    __syncthreads();

    if (tid < 64) {
        float xv[16] = { x0.x, x0.y, x0.z, x0.w,  x1.x, x1.y, x1.z, x1.w,
                         x2.x, x2.y, x2.z, x2.w,  x3.x, x3.y, x3.z, x3.w };
        float g = 0.f;
        #pragma unroll
        for (int k = 0; k < 16; ++k) g += xv[k] * wa2[k];
        float e = expf(g);           // |g| <~ 3: safe without max-shift

        float p[17];
        #pragma unroll
        for (int k = 0; k < 16; ++k) p[k] = e * xv[k];
        p[16] = e;

        #pragma unroll
        for (int off = 16; off > 0; off >>= 1) {
            #pragma unroll
            for (int i = 0; i < 17; ++i)
                p[i] += __shfl_down_sync(0xffffffffu, p[i], off);
        }
        if (lane == 0) {
            #pragma unroll
            for (int i = 0; i < 17; ++i) wsum[warp][i] = p[i];
        }
    }
    __syncthreads();

    if (tid < 17)
        g_part[tid * NB + bid] = wsum[0][tid] + wsum[1][tid];
    __syncthreads();   // intra-CTA: partial stores happen-before thread 0's release

    // ---- global barrier: release arrive, acquire-load poll ----
    if (tid == 0) {
        atom_add_release_gpu(&g_arrive);
        while (ld_acquire_gpu(&g_arrive) < NB) { }
    }
    __syncthreads();

    // ---- stage B1: warp w (w<17) reduces column w: 128 floats, 4/lane ----
    if (warp < 17) {
        const float* col = g_part + warp * NB;
        float v = col[lane] + col[lane + 32] + col[lane + 64] + col[lane + 96];
        #pragma unroll
        for (int off = 16; off > 0; off >>= 1)
            v += __shfl_down_sync(0xffffffffu, v, off);
        if (lane == 0) red[warp] = v;
    }
    __syncthreads();

    // ---- stage B2: out_row[h*16+d] = (nvec @ Wk[h]) / Z ----
    if (tid < 128) {
        float invZ = 1.0f / red[16];
        float s = 0.f;
        #pragma unroll
        for (int k = 0; k < 16; ++k) s += red[k] * wcol[k];
        orow[tid] = s * invZ;
    }
    __syncthreads();

    // ---- stage B3: broadcast 64 rows, exactly 2 STG.128 per thread ----
    {
        int c4 = tid & 31;           // float4 column 0..31
        int r  = tid >> 5;           // 0..31
        float4 val = make_float4(orow[c4 * 4 + 0], orow[c4 * 4 + 1],
                                 orow[c4 * 4 + 2], orow[c4 * 4 + 3]);
        float4* o4 = reinterpret_cast<float4*>(out);
        size_t base = (size_t)(bid * 64) * 32;
        o4[base + (size_t)r * 32 + c4]        = val;
        o4[base + (size_t)(r + 32) * 32 + c4] = val;
    }

    // ---- counter reset for next graph replay (last departer) ----
    __syncthreads();
    if (tid == 0) {
        unsigned int old = atomicAdd(&g_depart, 1);
        if (old == NB - 1) {
            atomicExch(&g_arrive, 0u);
            atomicExch(&g_depart, 0u);
        }
    }
}

extern "C" void kernel_launch(void* const* d_in, const int* in_sizes, int n_in,
                              void* d_out, int out_size) {
    const float* x  = (const float*)d_in[0];  // (8192,16)
    const float* W  = (const float*)d_in[1];  // (16,18)
    const float* a  = (const float*)d_in[2];  // (36,1)
    const float* Wk = (const float*)d_in[3];  // (8,16,16)
    float* out = (float*)d_out;               // (8192,128)

    fused_kernel<<<NB, NT>>>(x, W, a, Wk, out);
}

// round 11
// speedup vs baseline: 1.1985x; 1.1985x over previous
#include <cuda_runtime.h>

// softmax(f[n]+g[m]) over m cancels f[n] -> all output rows identical.
// Single fused kernel, 128 CTAs x 544 thr (one wave):
//   stage A: 64 thr/CTA reduce 64 rows of x with exp(g) weights -> 17-float partial
//   barrier: RED.release arrive (no ATOMG serialization) + acquire-LDG poll by tid0
//   stage B: 17 warps reduce partials, 128 thr compute row, 512 thr broadcast 4MB
//   reset:   RED depart; only bid0 polls + resets (no serialized kernel tail)

#define NB 128
#define NT 544
#define D_IN 16
#define DH   18

__device__ float g_part[17 * NB];        // [col][block]
__device__ unsigned int g_arrive = 0;
__device__ unsigned int g_depart = 0;

__device__ __forceinline__ void red_add_release_gpu(unsigned int* p) {
    asm volatile("red.release.gpu.global.add.u32 [%0], 1;" :: "l"(p) : "memory");
}
__device__ __forceinline__ void red_add_relaxed_gpu(unsigned int* p) {
    asm volatile("red.relaxed.gpu.global.add.u32 [%0], 1;" :: "l"(p) : "memory");
}
__device__ __forceinline__ unsigned int ld_acquire_gpu(const unsigned int* p) {
    unsigned int v;
    asm volatile("ld.acquire.gpu.global.u32 %0, [%1];" : "=r"(v) : "l"(p) : "memory");
    return v;
}
__device__ __forceinline__ void st_relaxed_gpu(unsigned int* p, unsigned int v) {
    asm volatile("st.relaxed.gpu.global.u32 [%0], %1;" :: "l"(p), "r"(v) : "memory");
}

__global__ void __launch_bounds__(NT, 1) fused_kernel(
    const float* __restrict__ x,
    const float* __restrict__ W,
    const float* __restrict__ a,
    const float* __restrict__ Wk,
    float* __restrict__ out)
{
    __shared__ float wa2[16];
    __shared__ float wsum[2][17];
    __shared__ float red[17];
    __shared__ float orow[128];
    int tid  = threadIdx.x;
    int warp = tid >> 5, lane = tid & 31;
    int bid  = blockIdx.x;

    // ---- prologue: independent loads first ----
    float4 x0, x1, x2, x3;
    if (tid < 64) {
        const float4* xr = reinterpret_cast<const float4*>(
            x + (size_t)(bid * 64 + tid) * D_IN);
        x0 = xr[0]; x1 = xr[1]; x2 = xr[2]; x3 = xr[3];
    }
    if (tid >= 64 && tid < 80) {       // warp 2: wa2 = W @ a2
        int r = tid - 64;
        float s = 0.f;
        #pragma unroll
        for (int j = 0; j < DH; ++j) s += W[r * DH + j] * a[DH + j];
        wa2[r] = s;
    }
    float wcol[16];                     // Wk column, kept in regs across barrier
    if (tid < 128) {
        int h = tid >> 4, d = tid & 15;
        const float* Wh = Wk + h * (D_IN * D_IN);
        #pragma unroll
        for (int k = 0; k < 16; ++k) wcol[k] = Wh[k * 16 + d];
    }
    __syncthreads();

    // ---- stage A: exp-weighted reduce of this CTA's 64 rows ----
    if (tid < 64) {
        float xv[16] = { x0.x, x0.y, x0.z, x0.w,  x1.x, x1.y, x1.z, x1.w,
                         x2.x, x2.y, x2.z, x2.w,  x3.x, x3.y, x3.z, x3.w };
        float g = 0.f;
        #pragma unroll
        for (int k = 0; k < 16; ++k) g += xv[k] * wa2[k];
        float e = expf(g);              // |g| <~ 3: safe without max-shift

        float p[17];
        #pragma unroll
        for (int k = 0; k < 16; ++k) p[k] = e * xv[k];
        p[16] = e;

        #pragma unroll
        for (int off = 16; off > 0; off >>= 1) {
            #pragma unroll
            for (int i = 0; i < 17; ++i)
                p[i] += __shfl_down_sync(0xffffffffu, p[i], off);
        }
        if (lane == 0) {
            #pragma unroll
            for (int i = 0; i < 17; ++i) wsum[warp][i] = p[i];
        }
    }
    __syncthreads();

    if (tid < 17)
        g_part[tid * NB + bid] = wsum[0][tid] + wsum[1][tid];
    __syncthreads();   // partial stores happen-before tid0's release-arrive

    // ---- global barrier: RED arrive (no serialization), acquire poll ----
    if (tid == 0) {
        red_add_release_gpu(&g_arrive);
        while (ld_acquire_gpu(&g_arrive) < NB) { }
    }
    __syncthreads();

    // ---- stage B1: warp w (<17) reduces column w: 128 floats, 4/lane ----
    if (warp < 17) {
        const float* col = g_part + warp * NB;
        float v = col[lane] + col[lane + 32] + col[lane + 64] + col[lane + 96];
        #pragma unroll
        for (int off = 16; off > 0; off >>= 1)
            v += __shfl_down_sync(0xffffffffu, v, off);
        if (lane == 0) red[warp] = v;
    }
    __syncthreads();

    // ---- stage B2: out_row[h*16+d] = (nvec @ Wk[h]) / Z ----
    if (tid < 128) {
        float invZ = 1.0f / red[16];
        float s = 0.f;
        #pragma unroll
        for (int k = 0; k < 16; ++k) s += red[k] * wcol[k];
        orow[tid] = s * invZ;
    }
    __syncthreads();

    // ---- stage B3: broadcast 64 rows = 2048 float4; 512 thr x 4 stores ----
    if (tid < 512) {
        int c4 = tid & 31;
        int r0 = tid >> 5;              // 0..15
        float4 val = make_float4(orow[c4 * 4 + 0], orow[c4 * 4 + 1],
                                 orow[c4 * 4 + 2], orow[c4 * 4 + 3]);
        float4* o4 = reinterpret_cast<float4*>(out);
        size_t base = (size_t)(bid * 64) * 32;
        #pragma unroll
        for (int i = 0; i < 4; ++i)
            o4[base + (size_t)(r0 + i * 16) * 32 + c4] = val;
    }

    // ---- replay reset: RED depart; only bid0 polls & resets ----
    __syncthreads();
    if (tid == 0) {
        red_add_relaxed_gpu(&g_depart);
        if (bid == 0) {
            while (ld_acquire_gpu(&g_depart) < NB) { }
            st_relaxed_gpu(&g_arrive, 0u);
            st_relaxed_gpu(&g_depart, 0u);
        }
    }
}

extern "C" void kernel_launch(void* const* d_in, const int* in_sizes, int n_in,
                              void* d_out, int out_size) {
    const float* x  = (const float*)d_in[0];  // (8192,16)
    const float* W  = (const float*)d_in[1];  // (16,18)
    const float* a  = (const float*)d_in[2];  // (36,1)
    const float* Wk = (const float*)d_in[3];  // (8,16,16)
    float* out = (float*)d_out;               // (8192,128)

    fused_kernel<<<NB, NT>>>(x, W, a, Wk, out);
}

// round 13
// speedup vs baseline: 1.2030x; 1.0037x over previous
#include <cuda_runtime.h>

// softmax(f[n]+g[m]) over m cancels f[n] -> all output rows identical.
// Single fused kernel, 64 CTAs x 544 thr (17 warps — stage B1 NEEDS 17):
//   stage A: 128 thr/CTA reduce 128 rows of x with exp(g) weights -> 17-float partial
//   barrier: TICKET barrier (atom.add.release returns old; no reset, replay-safe)
//   stage B: 17 warps reduce partials, 128 thr compute row, 512 thr broadcast 4MB.

#define NB 64
#define NT 544          // 17 warps: stage B1 reduces 17 columns, one per warp
#define D_IN 16
#define DH   18

__device__ float g_part[17 * NB];            // [col][block]
__device__ unsigned int g_arrive = 0;        // monotonic ticket counter (never reset)

__device__ __forceinline__ unsigned int atom_add_release_gpu(unsigned int* p) {
    unsigned int old;
    asm volatile("atom.add.release.gpu.global.u32 %0, [%1], 1;"
                 : "=r"(old) : "l"(p) : "memory");
    return old;
}
__device__ __forceinline__ unsigned int ld_acquire_gpu(const unsigned int* p) {
    unsigned int v;
    asm volatile("ld.acquire.gpu.global.u32 %0, [%1];" : "=r"(v) : "l"(p) : "memory");
    return v;
}

__global__ void __launch_bounds__(NT, 1) fused_kernel(
    const float* __restrict__ x,
    const float* __restrict__ W,
    const float* __restrict__ a,
    const float* __restrict__ Wk,
    float* __restrict__ out)
{
    __shared__ float wa2[16];
    __shared__ float wsum[4][17];
    __shared__ float red[17];
    __shared__ float orow[128];
    int tid  = threadIdx.x;
    int warp = tid >> 5, lane = tid & 31;
    int bid  = blockIdx.x;

    // ---- prologue: all independent loads issued first ----
    float4 x0, x1, x2, x3;
    if (tid < 128) {
        const float4* xr = reinterpret_cast<const float4*>(
            x + (size_t)(bid * 128 + tid) * D_IN);
        x0 = xr[0]; x1 = xr[1]; x2 = xr[2]; x3 = xr[3];
    }
    if (tid >= 128 && tid < 144) {      // warp 4: wa2 = W @ a2
        int r = tid - 128;
        float s = 0.f;
        #pragma unroll
        for (int j = 0; j < DH; ++j) s += W[r * DH + j] * a[DH + j];
        wa2[r] = s;
    }
    float wcol[16];                      // Wk column, in regs across the barrier
    if (tid < 128) {
        int h = tid >> 4, d = tid & 15;
        const float* Wh = Wk + h * (D_IN * D_IN);
        #pragma unroll
        for (int k = 0; k < 16; ++k) wcol[k] = Wh[k * 16 + d];
    }
    __syncthreads();

    // ---- stage A: exp-weighted reduce of this CTA's 128 rows ----
    if (tid < 128) {
        float xv[16] = { x0.x, x0.y, x0.z, x0.w,  x1.x, x1.y, x1.z, x1.w,
                         x2.x, x2.y, x2.z, x2.w,  x3.x, x3.y, x3.z, x3.w };
        float g = 0.f;
        #pragma unroll
        for (int k = 0; k < 16; ++k) g += xv[k] * wa2[k];
        float e = expf(g);               // |g| <~ 3: safe without max-shift

        float p[17];
        #pragma unroll
        for (int k = 0; k < 16; ++k) p[k] = e * xv[k];
        p[16] = e;

        #pragma unroll
        for (int off = 16; off > 0; off >>= 1) {
            #pragma unroll
            for (int i = 0; i < 17; ++i)
                p[i] += __shfl_down_sync(0xffffffffu, p[i], off);
        }
        if (lane == 0) {
            #pragma unroll
            for (int i = 0; i < 17; ++i) wsum[warp][i] = p[i];
        }
    }
    __syncthreads();

    if (tid < 17)
        g_part[tid * NB + bid] =
            wsum[0][tid] + wsum[1][tid] + wsum[2][tid] + wsum[3][tid];
    __syncthreads();   // partial stores happen-before tid0's release-arrive

    // ---- ticket barrier: no reset, monotonic counter (2^32 % NB == 0) ----
    if (tid == 0) {
        unsigned int old = atom_add_release_gpu(&g_arrive);
        unsigned int target = (old / NB + 1u) * NB;   // end of this round
        while (ld_acquire_gpu(&g_arrive) < target) { }
    }
    __syncthreads();

    // ---- stage B1: warp w (w<17) reduces column w: 64 floats, 2/lane ----
    if (warp < 17) {
        const float* col = g_part + warp * NB;
        float v = col[lane] + col[lane + 32];
        #pragma unroll
        for (int off = 16; off > 0; off >>= 1)
            v += __shfl_down_sync(0xffffffffu, v, off);
        if (lane == 0) red[warp] = v;
    }
    __syncthreads();

    // ---- stage B2: out_row[h*16+d] = (nvec @ Wk[h]) / Z ----
    if (tid < 128) {
        float invZ = 1.0f / red[16];
        float s = 0.f;
        #pragma unroll
        for (int k = 0; k < 16; ++k) s += red[k] * wcol[k];
        orow[tid] = s * invZ;
    }
    __syncthreads();

    // ---- stage B3: broadcast 128 rows = 4096 float4; 512 thr x 8 stores ----
    if (tid < 512) {
        int c4 = tid & 31;               // float4 column 0..31
        int r0 = tid >> 5;               // 0..15
        float4 val = make_float4(orow[c4 * 4 + 0], orow[c4 * 4 + 1],
                                 orow[c4 * 4 + 2], orow[c4 * 4 + 3]);
        float4* o4 = reinterpret_cast<float4*>(out);
        size_t base = (size_t)(bid * 128) * 32;
        #pragma unroll
        for (int i = 0; i < 8; ++i)
            o4[base + (size_t)(r0 + i * 16) * 32 + c4] = val;
    }
    // no tail: kernel ends at last store
}

extern "C" void kernel_launch(void* const* d_in, const int* in_sizes, int n_in,
                              void* d_out, int out_size) {
    const float* x  = (const float*)d_in[0];  // (8192,16)
    const float* W  = (const float*)d_in[1];  // (16,18)
    const float* a  = (const float*)d_in[2];  // (36,1)
    const float* Wk = (const float*)d_in[3];  // (8,16,16)
    float* out = (float*)d_out;               // (8192,128)

    fused_kernel<<<NB, NT>>>(x, W, a, Wk, out);
}